// round 1
// baseline (speedup 1.0000x reference)
#include <cuda_runtime.h>
#include <cuda_bf16.h>
#include <math.h>

// Problem constants
#define L_DIM   2048
#define E_DIM   512
#define EPT_DIM 300
#define H_DIM   16
#define KBIG    (H_DIM * EPT_DIM)   // 4800

// Scratch (allocation-free rule: __device__ globals)
__device__ float g_Z [L_DIM * KBIG];     // 39.3 MB
__device__ float g_S [L_DIM * L_DIM];    // 16.8 MB (scores -> adj in place)
__device__ float g_T0[L_DIM * E_DIM];
__device__ float g_X1[L_DIM * E_DIM];
__device__ float g_T1[L_DIM * E_DIM];

// ---------------------------------------------------------------------------
// Kernel 1: build Z[l, h*300+e] = x[l,e]*Wpt[h,e]^2 / (max(norm_{h,l},eps)*sqrt(H))
// One block per l. 256 threads; each thread owns e and e+256 (e+256 < 300 only
// for tid < 44).
// ---------------------------------------------------------------------------
__global__ __launch_bounds__(256) void compute_z(
    const float* __restrict__ xpt,   // [L, 300]
    const float* __restrict__ Wpt,   // [16, 300]
    float* __restrict__ Z)           // [L, 4800]
{
    const int l   = blockIdx.x;
    const int tid = threadIdx.x;
    __shared__ float sx[EPT_DIM];
    __shared__ float red[8];

    for (int e = tid; e < EPT_DIM; e += 256) sx[e] = xpt[(size_t)l * EPT_DIM + e];
    __syncthreads();

    const int e0 = tid;
    const int e1 = tid + 256;

    for (int h = 0; h < H_DIM; h++) {
        float v0 = 0.f, v1 = 0.f;
        if (e0 < EPT_DIM) { float w = Wpt[h * EPT_DIM + e0]; v0 = sx[e0] * w * w; }
        if (e1 < EPT_DIM) { float w = Wpt[h * EPT_DIM + e1]; v1 = sx[e1] * w * w; }
        float ss = v0 * v0 + v1 * v1;
        #pragma unroll
        for (int o = 16; o; o >>= 1) ss += __shfl_xor_sync(0xffffffffu, ss, o);
        if ((tid & 31) == 0) red[tid >> 5] = ss;
        __syncthreads();
        float tot = red[0] + red[1] + red[2] + red[3] +
                    red[4] + red[5] + red[6] + red[7];
        // h / max(norm, 1e-12), folded with 1/sqrt(H)=0.25
        float inv = 0.25f / fmaxf(sqrtf(tot), 1e-12f);
        float* zrow = Z + (size_t)l * KBIG + h * EPT_DIM;
        if (e0 < EPT_DIM) zrow[e0] = v0 * inv;
        if (e1 < EPT_DIM) zrow[e1] = v1 * inv;
        __syncthreads();
    }
}

// ---------------------------------------------------------------------------
// Kernel 2: generic fp32 SGEMM, C = A(MxK) @ op(B), op(B)=B(KxN) or B^T (B is NxK).
// 128x128 block tile, BK=16, 256 threads, 8x8 per-thread microtile.
// Assumes M,N multiple of 128, K multiple of 16 (true for all call sites),
// and all row strides multiple of 4 floats (true: 4800/512/2048).
// ---------------------------------------------------------------------------
template <int TRANS_B, int RELU>
__global__ __launch_bounds__(256) void sgemm128(
    const float* __restrict__ A, const float* __restrict__ B,
    float* __restrict__ C, int M, int N, int K)
{
    __shared__ float As[16][132];
    __shared__ float Bs[16][132];

    const int tid = threadIdx.x;
    const int tx  = tid & 15;       // 16 cols of threads
    const int ty  = tid >> 4;       // 16 rows of threads
    const int bm  = blockIdx.y << 7;
    const int bn  = blockIdx.x << 7;

    float acc[8][8];
    #pragma unroll
    for (int i = 0; i < 8; i++)
        #pragma unroll
        for (int j = 0; j < 8; j++) acc[i][j] = 0.f;

    for (int k0 = 0; k0 < K; k0 += 16) {
        // --- load A tile: 128 rows x 16 cols, transposed into As[k][m]
        #pragma unroll
        for (int t = 0; t < 2; t++) {
            int idx = tid + t * 256;
            int r = idx >> 2, c = (idx & 3) << 2;
            float4 v = *(const float4*)(A + (size_t)(bm + r) * K + k0 + c);
            As[c + 0][r] = v.x; As[c + 1][r] = v.y;
            As[c + 2][r] = v.z; As[c + 3][r] = v.w;
        }
        // --- load B tile into Bs[k][n]
        if (TRANS_B) {
            // B is [N, K]; tile rows are n, cols are k (contiguous)
            #pragma unroll
            for (int t = 0; t < 2; t++) {
                int idx = tid + t * 256;
                int r = idx >> 2, c = (idx & 3) << 2;
                float4 v = *(const float4*)(B + (size_t)(bn + r) * K + k0 + c);
                Bs[c + 0][r] = v.x; Bs[c + 1][r] = v.y;
                Bs[c + 2][r] = v.z; Bs[c + 3][r] = v.w;
            }
        } else {
            // B is [K, N]; tile rows are k, cols are n (contiguous)
            #pragma unroll
            for (int t = 0; t < 2; t++) {
                int idx = tid + t * 256;
                int r = idx >> 5, c = (idx & 31) << 2;
                float4 v = *(const float4*)(B + (size_t)(k0 + r) * N + bn + c);
                *(float4*)&Bs[r][c] = v;
            }
        }
        __syncthreads();

        #pragma unroll
        for (int kk = 0; kk < 16; kk++) {
            float a[8], b[8];
            *(float4*)(a)     = *(const float4*)&As[kk][ty * 8];
            *(float4*)(a + 4) = *(const float4*)&As[kk][ty * 8 + 4];
            *(float4*)(b)     = *(const float4*)&Bs[kk][tx * 8];
            *(float4*)(b + 4) = *(const float4*)&Bs[kk][tx * 8 + 4];
            #pragma unroll
            for (int i = 0; i < 8; i++)
                #pragma unroll
                for (int j = 0; j < 8; j++)
                    acc[i][j] = fmaf(a[i], b[j], acc[i][j]);
        }
        __syncthreads();
    }

    #pragma unroll
    for (int i = 0; i < 8; i++) {
        float* crow = C + (size_t)(bm + ty * 8 + i) * N + bn + tx * 8;
        float4 v0, v1;
        v0.x = acc[i][0]; v0.y = acc[i][1]; v0.z = acc[i][2]; v0.w = acc[i][3];
        v1.x = acc[i][4]; v1.y = acc[i][5]; v1.z = acc[i][6]; v1.w = acc[i][7];
        if (RELU) {
            v0.x = fmaxf(v0.x, 0.f); v0.y = fmaxf(v0.y, 0.f);
            v0.z = fmaxf(v0.z, 0.f); v0.w = fmaxf(v0.w, 0.f);
            v1.x = fmaxf(v1.x, 0.f); v1.y = fmaxf(v1.y, 0.f);
            v1.z = fmaxf(v1.z, 0.f); v1.w = fmaxf(v1.w, 0.f);
        }
        *(float4*)(crow)     = v0;
        *(float4*)(crow + 4) = v1;
    }
}

// ---------------------------------------------------------------------------
// Kernel 3: in-place masked softmax per row:
//   s' = (s >= 0.1) ? s : -1e20 ; row = softmax(s')
// Diagonal cosine is exactly ||z||^2 = 1 >= 0.1, so every row has a kept entry.
// ---------------------------------------------------------------------------
__global__ __launch_bounds__(256) void masked_softmax(float* __restrict__ S)
{
    __shared__ float red[8];
    const int r   = blockIdx.x;
    const int tid = threadIdx.x;
    float* row = S + (size_t)r * L_DIM;

    float m = -1e30f;
    for (int c = tid; c < L_DIM; c += 256) {
        float s = row[c];
        if (s >= 0.1f) m = fmaxf(m, s);
    }
    #pragma unroll
    for (int o = 16; o; o >>= 1) m = fmaxf(m, __shfl_xor_sync(0xffffffffu, m, o));
    if ((tid & 31) == 0) red[tid >> 5] = m;
    __syncthreads();
    float M = fmaxf(fmaxf(fmaxf(red[0], red[1]), fmaxf(red[2], red[3])),
                    fmaxf(fmaxf(red[4], red[5]), fmaxf(red[6], red[7])));
    __syncthreads();

    float sum = 0.f;
    for (int c = tid; c < L_DIM; c += 256) {
        float s = row[c];
        float e = (s >= 0.1f) ? expf(s - M) : 0.f;
        row[c] = e;
        sum += e;
    }
    #pragma unroll
    for (int o = 16; o; o >>= 1) sum += __shfl_xor_sync(0xffffffffu, sum, o);
    if ((tid & 31) == 0) red[tid >> 5] = sum;
    __syncthreads();
    float T = red[0] + red[1] + red[2] + red[3] +
              red[4] + red[5] + red[6] + red[7];
    float inv = 1.f / T;
    for (int c = tid; c < L_DIM; c += 256) row[c] *= inv;
}

// ---------------------------------------------------------------------------
// Launch
// ---------------------------------------------------------------------------
extern "C" void kernel_launch(void* const* d_in, const int* in_sizes, int n_in,
                              void* d_out, int out_size)
{
    const float* Lemb = (const float*)d_in[0];   // [2048, 512]
    const float* Xpt  = (const float*)d_in[1];   // [2048, 300]
    const float* Wpt  = (const float*)d_in[2];   // [16, 300]
    const float* W0   = (const float*)d_in[3];   // [512, 512]
    const float* W1   = (const float*)d_in[4];   // [512, 512]
    float* out = (float*)d_out;                  // [2048, 512]

    float *Z, *S, *T0, *X1, *T1;
    cudaGetSymbolAddress((void**)&Z,  g_Z);
    cudaGetSymbolAddress((void**)&S,  g_S);
    cudaGetSymbolAddress((void**)&T0, g_T0);
    cudaGetSymbolAddress((void**)&X1, g_X1);
    cudaGetSymbolAddress((void**)&T1, g_T1);

    // 1) Z = per-head-normalized weighted embedding, flattened [2048, 4800]
    compute_z<<<L_DIM, 256>>>(Xpt, Wpt, Z);

    // 2) scores = Z @ Z^T  (collapsed per-head mean cosine)
    sgemm128<1, 0><<<dim3(L_DIM / 128, L_DIM / 128), 256>>>(Z, Z, S,
                                                            L_DIM, L_DIM, KBIG);

    // 3) adj = softmax(threshold(scores)) in place
    masked_softmax<<<L_DIM, 256>>>(S);

    // 4) T0 = Lemb @ W0
    sgemm128<0, 0><<<dim3(E_DIM / 128, L_DIM / 128), 256>>>(Lemb, W0, T0,
                                                            L_DIM, E_DIM, E_DIM);
    // 5) X1 = relu(adj @ T0)
    sgemm128<0, 1><<<dim3(E_DIM / 128, L_DIM / 128), 256>>>(S, T0, X1,
                                                            L_DIM, E_DIM, L_DIM);
    // 6) T1 = X1 @ W1
    sgemm128<0, 0><<<dim3(E_DIM / 128, L_DIM / 128), 256>>>(X1, W1, T1,
                                                            L_DIM, E_DIM, E_DIM);
    // 7) out = relu(adj @ T1)
    sgemm128<0, 1><<<dim3(E_DIM / 128, L_DIM / 128), 256>>>(S, T1, out,
                                                            L_DIM, E_DIM, L_DIM);
}

// round 2
// speedup vs baseline: 2.1227x; 2.1227x over previous
#include <cuda_runtime.h>
#include <cuda_bf16.h>
#include <math.h>

// Problem constants
#define L_DIM   2048
#define E_DIM   512
#define EPT_DIM 300
#define H_DIM   16
#define KBIG    (H_DIM * EPT_DIM)   // 4800

// Scratch (allocation-free rule: __device__ globals)
__device__ float g_Z [L_DIM * KBIG];     // 39.3 MB
__device__ float g_S [L_DIM * L_DIM];    // 16.8 MB (scores -> adj in place)
__device__ float g_T0[L_DIM * E_DIM];
__device__ float g_X1[L_DIM * E_DIM];
__device__ float g_T1[L_DIM * E_DIM];

// ---------------------------------------------------------------------------
// Kernel 1: Z[l, h*300+e] = x[l,e]*Wpt[h,e]^2 / (max(norm_{h,l},1e-12)*sqrt(H))
// ---------------------------------------------------------------------------
__global__ __launch_bounds__(256) void compute_z(
    const float* __restrict__ xpt,   // [L, 300]
    const float* __restrict__ Wpt,   // [16, 300]
    float* __restrict__ Z)           // [L, 4800]
{
    const int l   = blockIdx.x;
    const int tid = threadIdx.x;
    __shared__ float sx[EPT_DIM];
    __shared__ float red[8];

    for (int e = tid; e < EPT_DIM; e += 256) sx[e] = xpt[(size_t)l * EPT_DIM + e];
    __syncthreads();

    const int e0 = tid;
    const int e1 = tid + 256;

    for (int h = 0; h < H_DIM; h++) {
        float v0 = 0.f, v1 = 0.f;
        if (e0 < EPT_DIM) { float w = Wpt[h * EPT_DIM + e0]; v0 = sx[e0] * w * w; }
        if (e1 < EPT_DIM) { float w = Wpt[h * EPT_DIM + e1]; v1 = sx[e1] * w * w; }
        float ss = v0 * v0 + v1 * v1;
        #pragma unroll
        for (int o = 16; o; o >>= 1) ss += __shfl_xor_sync(0xffffffffu, ss, o);
        if ((tid & 31) == 0) red[tid >> 5] = ss;
        __syncthreads();
        float tot = red[0] + red[1] + red[2] + red[3] +
                    red[4] + red[5] + red[6] + red[7];
        float inv = 0.25f / fmaxf(sqrtf(tot), 1e-12f);   // 1/sqrt(H)=0.25 folded
        float* zrow = Z + (size_t)l * KBIG + h * EPT_DIM;
        if (e0 < EPT_DIM) zrow[e0] = v0 * inv;
        if (e1 < EPT_DIM) zrow[e1] = v1 * inv;
        __syncthreads();
    }
}

// ---------------------------------------------------------------------------
// Kernel 2: double-buffered fp32 GEMM.
//   C = A(MxK) @ op(B); op(B) = B[KxN] (TRANS_B=0) or B^T with B[NxK] (TRANS_B=1)
//   BMxBN block tile, BK=16, 256 threads, (BM/16)x(BN/16) per-thread microtile.
//   SYM=1: C is symmetric (A@A^T); only bx>=by tiles run, each writes its
//   transpose tile too.
// Requires: M%BM==0, N%BN==0, K%16==0, all row strides %4==0. True everywhere.
// ---------------------------------------------------------------------------
template <int BM, int BN, int TRANS_B, int RELU, int SYM>
__global__ __launch_bounds__(256, 1) void gemm_db(
    const float* __restrict__ A, const float* __restrict__ B,
    float* __restrict__ C, int M, int N, int K)
{
    constexpr int TM = BM / 16;            // rows per thread
    constexpr int TN = BN / 16;            // cols per thread
    constexpr int NA = BM / 64;            // float4 A-loads per thread
    constexpr int NB = (16 * BN) / 1024;   // float4 B-loads per thread

    __shared__ float As[2][16][BM + 4];
    __shared__ float Bs[2][16][BN + 4];

    const int bm = blockIdx.y * BM;
    const int bn = blockIdx.x * BN;
    if (SYM && blockIdx.x < blockIdx.y) return;

    const int tid = threadIdx.x;
    const int tx  = tid & 15;
    const int ty  = tid >> 4;

    float acc[TM][TN];
    #pragma unroll
    for (int i = 0; i < TM; i++)
        #pragma unroll
        for (int j = 0; j < TN; j++) acc[i][j] = 0.f;

    float4 ra[NA], rb[NB];

    // ---- global -> register loaders
    #define LD_A(k0)                                                          \
        _Pragma("unroll")                                                     \
        for (int t = 0; t < NA; t++) {                                        \
            int idx = tid + t * 256;                                          \
            int rr = idx >> 2, cc = (idx & 3) << 2;                           \
            ra[t] = *(const float4*)(A + (size_t)(bm + rr) * K + (k0) + cc);  \
        }
    #define LD_B(k0)                                                          \
        _Pragma("unroll")                                                     \
        for (int t = 0; t < NB; t++) {                                        \
            int idx = tid + t * 256;                                          \
            if (TRANS_B) {                                                    \
                int rr = idx >> 2, cc = (idx & 3) << 2;                       \
                rb[t] = *(const float4*)(B + (size_t)(bn + rr) * K + (k0) + cc); \
            } else {                                                          \
                int rr = idx / (BN / 4), cc = (idx % (BN / 4)) << 2;          \
                rb[t] = *(const float4*)(B + (size_t)((k0) + rr) * N + bn + cc); \
            }                                                                 \
        }
    // ---- register -> shared stores
    #define ST_A(buf)                                                         \
        _Pragma("unroll")                                                     \
        for (int t = 0; t < NA; t++) {                                        \
            int idx = tid + t * 256;                                          \
            int rr = idx >> 2, cc = (idx & 3) << 2;                           \
            As[buf][cc + 0][rr] = ra[t].x; As[buf][cc + 1][rr] = ra[t].y;     \
            As[buf][cc + 2][rr] = ra[t].z; As[buf][cc + 3][rr] = ra[t].w;     \
        }
    #define ST_B(buf)                                                         \
        _Pragma("unroll")                                                     \
        for (int t = 0; t < NB; t++) {                                        \
            int idx = tid + t * 256;                                          \
            if (TRANS_B) {                                                    \
                int rr = idx >> 2, cc = (idx & 3) << 2;                       \
                Bs[buf][cc + 0][rr] = rb[t].x; Bs[buf][cc + 1][rr] = rb[t].y; \
                Bs[buf][cc + 2][rr] = rb[t].z; Bs[buf][cc + 3][rr] = rb[t].w; \
            } else {                                                          \
                int rr = idx / (BN / 4), cc = (idx % (BN / 4)) << 2;          \
                *(float4*)&Bs[buf][rr][cc] = rb[t];                           \
            }                                                                 \
        }

    const int nk = K >> 4;
    LD_A(0); LD_B(0);
    ST_A(0); ST_B(0);
    __syncthreads();

    int cur = 0;
    for (int kt = 0; kt < nk; kt++) {
        if (kt + 1 < nk) {                       // prefetch next tile into regs
            int k0 = (kt + 1) << 4;
            LD_A(k0); LD_B(k0);
        }
        #pragma unroll
        for (int kk = 0; kk < 16; kk++) {
            float a[TM], b[TN];
            #pragma unroll
            for (int i = 0; i < TM; i += 4)
                *(float4*)(a + i) = *(const float4*)&As[cur][kk][ty * TM + i];
            #pragma unroll
            for (int j = 0; j < TN; j += 4)
                *(float4*)(b + j) = *(const float4*)&Bs[cur][kk][tx * TN + j];
            #pragma unroll
            for (int i = 0; i < TM; i++)
                #pragma unroll
                for (int j = 0; j < TN; j++)
                    acc[i][j] = fmaf(a[i], b[j], acc[i][j]);
        }
        if (kt + 1 < nk) { ST_A(cur ^ 1); ST_B(cur ^ 1); }
        __syncthreads();
        cur ^= 1;
    }

    // ---- epilogue
    #pragma unroll
    for (int i = 0; i < TM; i++) {
        float* crow = C + (size_t)(bm + ty * TM + i) * N + bn + tx * TN;
        #pragma unroll
        for (int j = 0; j < TN; j += 4) {
            float4 v;
            v.x = acc[i][j + 0]; v.y = acc[i][j + 1];
            v.z = acc[i][j + 2]; v.w = acc[i][j + 3];
            if (RELU) {
                v.x = fmaxf(v.x, 0.f); v.y = fmaxf(v.y, 0.f);
                v.z = fmaxf(v.z, 0.f); v.w = fmaxf(v.w, 0.f);
            }
            *(float4*)(crow + j) = v;
        }
    }
    if (SYM && blockIdx.x > blockIdx.y) {
        // write the transposed tile: C[bn+tx*TN+j][bm+ty*TM+i]
        #pragma unroll
        for (int j = 0; j < TN; j++) {
            float* crow = C + (size_t)(bn + tx * TN + j) * N + bm + ty * TM;
            #pragma unroll
            for (int i = 0; i < TM; i += 4) {
                float4 v;
                v.x = acc[i + 0][j]; v.y = acc[i + 1][j];
                v.z = acc[i + 2][j]; v.w = acc[i + 3][j];
                *(float4*)(crow + i) = v;
            }
        }
    }
    #undef LD_A
    #undef LD_B
    #undef ST_A
    #undef ST_B
}

// ---------------------------------------------------------------------------
// Kernel 3: in-place masked softmax per row (diag == 1 >= 0.1, always kept)
// ---------------------------------------------------------------------------
__global__ __launch_bounds__(256) void masked_softmax(float* __restrict__ S)
{
    __shared__ float red[8];
    const int r   = blockIdx.x;
    const int tid = threadIdx.x;
    float* row = S + (size_t)r * L_DIM;

    float m = -1e30f;
    for (int c = tid; c < L_DIM; c += 256) {
        float s = row[c];
        if (s >= 0.1f) m = fmaxf(m, s);
    }
    #pragma unroll
    for (int o = 16; o; o >>= 1) m = fmaxf(m, __shfl_xor_sync(0xffffffffu, m, o));
    if ((tid & 31) == 0) red[tid >> 5] = m;
    __syncthreads();
    float M = fmaxf(fmaxf(fmaxf(red[0], red[1]), fmaxf(red[2], red[3])),
                    fmaxf(fmaxf(red[4], red[5]), fmaxf(red[6], red[7])));
    __syncthreads();

    float sum = 0.f;
    for (int c = tid; c < L_DIM; c += 256) {
        float s = row[c];
        float e = (s >= 0.1f) ? expf(s - M) : 0.f;
        row[c] = e;
        sum += e;
    }
    #pragma unroll
    for (int o = 16; o; o >>= 1) sum += __shfl_xor_sync(0xffffffffu, sum, o);
    if ((tid & 31) == 0) red[tid >> 5] = sum;
    __syncthreads();
    float T = red[0] + red[1] + red[2] + red[3] +
              red[4] + red[5] + red[6] + red[7];
    float inv = 1.f / T;
    for (int c = tid; c < L_DIM; c += 256) row[c] *= inv;
}

// ---------------------------------------------------------------------------
// Launch
// ---------------------------------------------------------------------------
extern "C" void kernel_launch(void* const* d_in, const int* in_sizes, int n_in,
                              void* d_out, int out_size)
{
    const float* Lemb = (const float*)d_in[0];   // [2048, 512]
    const float* Xpt  = (const float*)d_in[1];   // [2048, 300]
    const float* Wpt  = (const float*)d_in[2];   // [16, 300]
    const float* W0   = (const float*)d_in[3];   // [512, 512]
    const float* W1   = (const float*)d_in[4];   // [512, 512]
    float* out = (float*)d_out;                  // [2048, 512]

    float *Z, *S, *T0, *X1, *T1;
    cudaGetSymbolAddress((void**)&Z,  g_Z);
    cudaGetSymbolAddress((void**)&S,  g_S);
    cudaGetSymbolAddress((void**)&T0, g_T0);
    cudaGetSymbolAddress((void**)&X1, g_X1);
    cudaGetSymbolAddress((void**)&T1, g_T1);

    // 1) Z = per-head-normalized weighted embedding, flattened [2048, 4800]
    compute_z<<<L_DIM, 256>>>(Xpt, Wpt, Z);

    // 2) scores = Z @ Z^T, symmetric: only upper-triangle tiles (136 CTAs, 1 wave)
    gemm_db<128, 128, 1, 0, 1><<<dim3(L_DIM / 128, L_DIM / 128), 256>>>(
        Z, Z, S, L_DIM, L_DIM, KBIG);

    // 3) adj = softmax(threshold(scores)) in place
    masked_softmax<<<L_DIM, 256>>>(S);

    // 4) T0 = Lemb @ W0           (128 CTAs, 1 wave)
    gemm_db<128, 64, 0, 0, 0><<<dim3(E_DIM / 64, L_DIM / 128), 256>>>(
        Lemb, W0, T0, L_DIM, E_DIM, E_DIM);
    // 5) X1 = relu(adj @ T0)
    gemm_db<128, 64, 0, 1, 0><<<dim3(E_DIM / 64, L_DIM / 128), 256>>>(
        S, T0, X1, L_DIM, E_DIM, L_DIM);
    // 6) T1 = X1 @ W1
    gemm_db<128, 64, 0, 0, 0><<<dim3(E_DIM / 64, L_DIM / 128), 256>>>(
        X1, W1, T1, L_DIM, E_DIM, E_DIM);
    // 7) out = relu(adj @ T1)
    gemm_db<128, 64, 0, 1, 0><<<dim3(E_DIM / 64, L_DIM / 128), 256>>>(
        S, T1, out, L_DIM, E_DIM, L_DIM);
}